// round 1
// baseline (speedup 1.0000x reference)
#include <cuda_runtime.h>
#include <cuda_bf16.h>
#include <math.h>

// Problem constants (fixed shapes per reference)
#define N_PROP   65536
#define N_GT     64
#define NCLS     81
#define TOTAL    512
#define MAX_POS  128
#define TPB      256
#define NB       (N_PROP / TPB)   // 256 blocks

// -------- device scratch (no allocations allowed) --------
__device__ int   g_flag[N_PROP];     // 0 = other, 1 = pos, 2 = neg
__device__ int   g_gtidx[N_PROP];    // argmax gt per proposal
__device__ int   g_blk_pos[NB];
__device__ int   g_blk_neg[NB];
__device__ int   g_off_pos[NB];
__device__ int   g_off_neg[NB];
__device__ int   g_off_non[NB];
__device__ int   g_pos_total;
__device__ int   g_neg_total;
__device__ int   g_pos_list[TOTAL];
__device__ int   g_neg_list[TOTAL];
__device__ int   g_non_list[TOTAL];  // fallback: first non-neg indices (matches argsort tail)
__device__ float g_ce[TOTAL];
__device__ float g_rg[TOTAL];

// ---------------- kernel 1: IoU + classification ----------------
__global__ void k_iou(const float* __restrict__ props, const float* __restrict__ gts, int n_gt) {
    __shared__ float4 sg[N_GT];
    __shared__ float  sga[N_GT];
    __shared__ int    cnt[2];
    int t = threadIdx.x;
    if (t < n_gt) {
        float4 g = ((const float4*)gts)[t];
        sg[t] = g;
        sga[t] = (g.z - g.x) * (g.w - g.y);
    }
    if (t < 2) cnt[t] = 0;
    __syncthreads();

    int i = blockIdx.x * TPB + t;
    float4 p = ((const float4*)props)[i];
    float pa = (p.z - p.x) * (p.w - p.y);

    float best = -1.0f;
    int bj = 0;
#pragma unroll 8
    for (int j = 0; j < N_GT; j++) {
        float4 g = sg[j];
        float ix = fminf(p.z, g.z) - fmaxf(p.x, g.x);
        float iy = fminf(p.w, g.w) - fmaxf(p.y, g.y);
        ix = fmaxf(ix, 0.0f);
        iy = fmaxf(iy, 0.0f);
        float inter = ix * iy;
        float iou = inter / (pa + sga[j] - inter + 1e-8f);
        if (iou > best) { best = iou; bj = j; }   // strict > keeps first occurrence (argmax)
    }
    int f = (best >= 0.5f) ? 1 : ((best >= 0.1f) ? 2 : 0);
    g_flag[i]  = f;
    g_gtidx[i] = bj;
    if (f == 1) atomicAdd(&cnt[0], 1);
    else if (f == 2) atomicAdd(&cnt[1], 1);
    __syncthreads();
    if (t == 0) {
        g_blk_pos[blockIdx.x] = cnt[0];
        g_blk_neg[blockIdx.x] = cnt[1];
    }
}

// ---------------- kernel 2: scan block counts ----------------
__global__ void k_scan() {
    __shared__ int sp[NB], sn[NB];
    int t = threadIdx.x;          // NB == TPB == 256
    int vp0 = g_blk_pos[t];
    int vn0 = g_blk_neg[t];
    sp[t] = vp0; sn[t] = vn0;
    for (int d = 1; d < NB; d <<= 1) {
        __syncthreads();
        int vp = (t >= d) ? sp[t - d] : 0;
        int vn = (t >= d) ? sn[t - d] : 0;
        __syncthreads();
        sp[t] += vp; sn[t] += vn;
    }
    __syncthreads();
    int op = sp[t] - vp0;                 // exclusive prefix of pos
    int on = sn[t] - vn0;                 // exclusive prefix of neg
    g_off_pos[t] = op;
    g_off_neg[t] = on;
    g_off_non[t] = t * TPB - on;          // exclusive prefix of non-neg = elems_before - neg_before
    if (t == NB - 1) {
        g_pos_total = sp[t];
        g_neg_total = sn[t];
    }
}

// ---------------- kernel 3: stable compaction of indices ----------------
__global__ void k_select() {
    int t = threadIdx.x;
    int i = blockIdx.x * TPB + t;
    int f = g_flag[i];
    int warp = t >> 5, lane = t & 31;
    const unsigned full = 0xffffffffu;
    unsigned bp = __ballot_sync(full, f == 1);
    unsigned bn = __ballot_sync(full, f == 2);
    __shared__ int wp[8], wn[8];
    if (lane == 0) { wp[warp] = __popc(bp); wn[warp] = __popc(bn); }
    __syncthreads();
    int pre_p = 0, pre_n = 0;
    for (int w = 0; w < warp; w++) { pre_p += wp[w]; pre_n += wn[w]; }
    unsigned lm = (1u << lane) - 1u;
    int neg_before = pre_n + __popc(bn & lm);  // # of neg threads before me in block
    if (f == 1) {
        int r = g_off_pos[blockIdx.x] + pre_p + __popc(bp & lm);
        if (r < TOTAL) g_pos_list[r] = i;
    } else if (f == 2) {
        int r = g_off_neg[blockIdx.x] + neg_before;
        if (r < TOTAL) g_neg_list[r] = i;
    }
    if (f != 2) {   // non-neg fallback list (matches argsort tail semantics)
        int r = g_off_non[blockIdx.x] + (t - neg_before);
        if (r < TOTAL) g_non_list[r] = i;
    }
}

// ---------------- kernel 4: per-slot CE + smooth-L1 ----------------
__device__ __forceinline__ float sl1(float d) {
    float ad = fabsf(d);
    return (ad < 1.0f) ? (0.5f * d * d) : (ad - 0.5f);
}

__global__ void k_loss(const float* __restrict__ props,
                       const float* __restrict__ gts,
                       const int*   __restrict__ gt_labels,
                       const float* __restrict__ score,
                       const float* __restrict__ txty) {
    const unsigned full = 0xffffffffu;
    int warp = threadIdx.x >> 5, lane = threadIdx.x & 31;
    int slot = blockIdx.x * (TPB / 32) + warp;   // grid 64 x 256 -> 512 slots
    if (slot >= TOTAL) return;

    int num_pos = min(g_pos_total, MAX_POS);
    int neg_total = g_neg_total;
    bool is_pos = slot < num_pos;
    int idx;
    if (is_pos) idx = g_pos_list[slot];
    else {
        int j = slot - num_pos;
        idx = (j < neg_total) ? g_neg_list[j] : g_non_list[j - neg_total];
    }
    int g = g_gtidx[idx];
    int lbl = is_pos ? gt_labels[g] : 0;

    const float* row = score + idx * NCLS;
    float m = -INFINITY;
    for (int c = lane; c < NCLS; c += 32) m = fmaxf(m, row[c]);
#pragma unroll
    for (int o = 16; o; o >>= 1) m = fmaxf(m, __shfl_xor_sync(full, m, o));
    float s = 0.0f;
    for (int c = lane; c < NCLS; c += 32) s += expf(row[c] - m);
#pragma unroll
    for (int o = 16; o; o >>= 1) s += __shfl_xor_sync(full, s, o);

    if (lane == 0) {
        float ce = m + logf(s) - row[lbl];
        float rg = 0.0f;
        if (is_pos) {
            float4 p  = ((const float4*)props)[idx];
            float4 gb = ((const float4*)gts)[g];
            float pw = p.z - p.x, ph = p.w - p.y;
            float pcx = p.x + 0.5f * pw, pcy = p.y + 0.5f * ph;
            float gw = gb.z - gb.x, gh = gb.w - gb.y;
            float gcx = gb.x + 0.5f * gw, gcy = gb.y + 0.5f * gh;
            float t0 = ((gcx - pcx) / pw) / 0.1f;
            float t1 = ((gcy - pcy) / ph) / 0.1f;
            float t2 = logf(gw / pw) / 0.2f;
            float t3 = logf(gh / ph) / 0.2f;
            const float* pr = txty + ((size_t)idx * NCLS + g) * 4;
            rg = sl1(pr[0] - t0) + sl1(pr[1] - t1) + sl1(pr[2] - t2) + sl1(pr[3] - t3);
        }
        g_ce[slot] = ce;
        g_rg[slot] = rg;
    }
}

// ---------------- kernel 5: deterministic final reduction ----------------
__global__ void k_final(float* __restrict__ out) {
    __shared__ float sc[256], sr[256];
    int t = threadIdx.x;
    sc[t] = g_ce[t] + g_ce[t + 256];
    sr[t] = g_rg[t] + g_rg[t + 256];
    for (int s = 128; s; s >>= 1) {
        __syncthreads();
        if (t < s) { sc[t] += sc[t + s]; sr[t] += sr[t + s]; }
    }
    __syncthreads();
    if (t == 0) {
        out[0] = sc[0] * (1.0f / (float)TOTAL);   // CLS_W = 1
        out[1] = sr[0] * (1.0f / (float)TOTAL);   // REG_W = 1
    }
}

extern "C" void kernel_launch(void* const* d_in, const int* in_sizes, int n_in,
                              void* d_out, int out_size) {
    // inputs per metadata order:
    // 0: image_shape (2 f32) -- unused
    // 1: rpn_proposals_bboxes (65536*4 f32)
    // 2: roi_score (65536*81 f32)
    // 3: roi_bboxes_txtytwth (65536*81*4 f32)
    // 4: gt_bboxes (64*4 f32)
    // 5: gt_labels (64 int32)
    const float* props = (const float*)d_in[1];
    const float* score = (const float*)d_in[2];
    const float* txty  = (const float*)d_in[3];
    const float* gts   = (const float*)d_in[4];
    const int*   glbl  = (const int*)d_in[5];
    float* out = (float*)d_out;
    int n_gt = in_sizes[4] / 4;

    k_iou   <<<NB, TPB>>>(props, gts, n_gt);
    k_scan  <<<1,  TPB>>>();
    k_select<<<NB, TPB>>>();
    k_loss  <<<TOTAL / (TPB / 32), TPB>>>(props, gts, glbl, score, txty);
    k_final <<<1, 256>>>(out);
}

// round 2
// speedup vs baseline: 1.0012x; 1.0012x over previous
#include <cuda_runtime.h>
#include <cuda_bf16.h>
#include <math.h>

#define N_PROP   65536
#define N_GT     64
#define NCLS     81
#define TOTAL    512
#define MAX_POS  128
#define TPB      256
#define NBLK     256            // N_PROP / TPB

// -------- device scratch --------
__device__ int   g_gtidx[N_PROP];
__device__ int   g_blk_pos[NBLK];
__device__ int   g_blk_neg[NBLK];
__device__ int   g_pos_list[TOTAL];
__device__ int   g_neg_list[TOTAL];
__device__ int   g_non_list[TOTAL];
__device__ float g_ce[TOTAL];
__device__ float g_rg[TOTAL];
__device__ int            g_bar_count;
__device__ volatile int   g_bar_gen;

// software global barrier: all NBLK blocks are co-resident (256 << 1184 capacity)
__device__ __forceinline__ void gbar() {
    __syncthreads();
    if (threadIdx.x == 0) {
        __threadfence();
        int gen = g_bar_gen;
        if (atomicAdd(&g_bar_count, 1) == NBLK - 1) {
            g_bar_count = 0;
            __threadfence();
            g_bar_gen = gen + 1;
        } else {
            while (g_bar_gen == gen) { }
        }
    }
    __syncthreads();
}

__device__ __forceinline__ float sl1(float d) {
    float ad = fabsf(d);
    return (ad < 1.0f) ? (0.5f * d * d) : (ad - 0.5f);
}

__global__ void __launch_bounds__(TPB)
k_fused(const float* __restrict__ props,
        const float* __restrict__ gts,
        const int*   __restrict__ gt_labels,
        const float* __restrict__ score,
        const float* __restrict__ txty,
        float* __restrict__ out,
        int n_gt) {
    __shared__ float4 sg[N_GT];
    __shared__ float  sga[N_GT];
    __shared__ int    sp[NBLK], sn[NBLK];
    __shared__ int    wp[8], wn[8];
    __shared__ int    s_numpos, s_negtot, s_offp, s_offn, s_offo;
    __shared__ float  red_c[TOTAL], red_r[TOTAL];

    const int t    = threadIdx.x;
    const int bid  = blockIdx.x;
    const int warp = t >> 5, lane = t & 31;
    const unsigned full = 0xffffffffu;

    // ============ phase 1: IoU + classify ============
    if (t < n_gt) {
        float4 g = ((const float4*)gts)[t];
        sg[t] = g;
        sga[t] = (g.z - g.x) * (g.w - g.y);
    }
    __syncthreads();

    const int i = bid * TPB + t;
    float4 p = ((const float4*)props)[i];
    float pa = (p.z - p.x) * (p.w - p.y);

    float best = -1.0f;
    int bj = 0;
#pragma unroll 8
    for (int j = 0; j < N_GT; j++) {
        float4 g = sg[j];
        float ix = fmaxf(fminf(p.z, g.z) - fmaxf(p.x, g.x), 0.0f);
        float iy = fmaxf(fminf(p.w, g.w) - fmaxf(p.y, g.y), 0.0f);
        float inter = ix * iy;
        float iou = inter / (pa + sga[j] - inter + 1e-8f);
        if (iou > best) { best = iou; bj = j; }   // strict > = first argmax
    }
    const int f = (best >= 0.5f) ? 1 : ((best >= 0.1f) ? 2 : 0);
    g_gtidx[i] = bj;

    unsigned bp = __ballot_sync(full, f == 1);
    unsigned bn = __ballot_sync(full, f == 2);
    if (lane == 0) { wp[warp] = __popc(bp); wn[warp] = __popc(bn); }
    __syncthreads();
    if (t == 0) {
        int cp = 0, cn = 0;
#pragma unroll
        for (int w = 0; w < 8; w++) { cp += wp[w]; cn += wn[w]; }
        g_blk_pos[bid] = cp;
        g_blk_neg[bid] = cn;
    }

    gbar();

    // ============ phase 2: replicated scan + stable select ============
    {
        int vp = __ldcg(&g_blk_pos[t]);
        int vn = __ldcg(&g_blk_neg[t]);
        sp[t] = vp; sn[t] = vn;
        for (int d = 1; d < NBLK; d <<= 1) {
            __syncthreads();
            int ap = (t >= d) ? sp[t - d] : 0;
            int an = (t >= d) ? sn[t - d] : 0;
            __syncthreads();
            sp[t] += ap; sn[t] += an;
        }
        __syncthreads();
        if (t == 0) {
            s_offp   = (bid > 0) ? sp[bid - 1] : 0;
            s_offn   = (bid > 0) ? sn[bid - 1] : 0;
            s_offo   = bid * TPB - s_offn;      // prefix of non-neg
            s_numpos = min(sp[NBLK - 1], MAX_POS);
            s_negtot = sn[NBLK - 1];
        }
        __syncthreads();

        int pre_p = 0, pre_n = 0;
        for (int w = 0; w < warp; w++) { pre_p += wp[w]; pre_n += wn[w]; }
        unsigned lm = (1u << lane) - 1u;
        int neg_before = pre_n + __popc(bn & lm);
        if (f == 1) {
            int r = s_offp + pre_p + __popc(bp & lm);
            if (r < TOTAL) g_pos_list[r] = i;
        } else if (f == 2) {
            int r = s_offn + neg_before;
            if (r < TOTAL) g_neg_list[r] = i;
        } else if (true) { }
        if (f != 2) {
            int r = s_offo + (t - neg_before);
            if (r < TOTAL) g_non_list[r] = i;
        }
    }

    gbar();

    // ============ phase 3: loss (2 warps/block -> 512 slots) ============
    if (warp < 2) {
        int slot = bid * 2 + warp;
        int num_pos = s_numpos;
        int neg_total = s_negtot;
        bool is_pos = slot < num_pos;
        int idx;
        if (is_pos) idx = __ldcg(&g_pos_list[slot]);
        else {
            int j = slot - num_pos;
            idx = (j < neg_total) ? __ldcg(&g_neg_list[j])
                                  : __ldcg(&g_non_list[j - neg_total]);
        }
        int g = __ldcg(&g_gtidx[idx]);
        int lbl = is_pos ? gt_labels[g] : 0;

        const float* row = score + (size_t)idx * NCLS;
        float v0 = row[lane];
        float v1 = row[lane + 32];
        float v2 = (lane + 64 < NCLS) ? row[lane + 64] : -INFINITY;
        float m = fmaxf(fmaxf(v0, v1), v2);
#pragma unroll
        for (int o = 16; o; o >>= 1) m = fmaxf(m, __shfl_xor_sync(full, m, o));
        float s = expf(v0 - m) + expf(v1 - m) + ((lane + 64 < NCLS) ? expf(v2 - m) : 0.0f);
#pragma unroll
        for (int o = 16; o; o >>= 1) s += __shfl_xor_sync(full, s, o);

        if (lane == 0) {
            float ce = m + logf(s) - row[lbl];
            float rg = 0.0f;
            if (is_pos) {
                float4 pp = ((const float4*)props)[idx];
                float4 gb = sg[g];
                float pw = pp.z - pp.x, ph = pp.w - pp.y;
                float pcx = pp.x + 0.5f * pw, pcy = pp.y + 0.5f * ph;
                float gw = gb.z - gb.x, gh = gb.w - gb.y;
                float gcx = gb.x + 0.5f * gw, gcy = gb.y + 0.5f * gh;
                float t0 = ((gcx - pcx) / pw) * 10.0f;
                float t1 = ((gcy - pcy) / ph) * 10.0f;
                float t2 = logf(gw / pw) * 5.0f;
                float t3 = logf(gh / ph) * 5.0f;
                const float* pr = txty + ((size_t)idx * NCLS + g) * 4;
                float4 pv = *(const float4*)pr;
                rg = sl1(pv.x - t0) + sl1(pv.y - t1) + sl1(pv.z - t2) + sl1(pv.w - t3);
            }
            g_ce[slot] = ce;
            g_rg[slot] = rg;
        }
    }

    gbar();

    // ============ phase 4: deterministic reduction (block 0) ============
    if (bid == 0) {
        red_c[t]       = __ldcg(&g_ce[t])       + __ldcg(&g_ce[t + 256]);
        red_r[t]       = __ldcg(&g_rg[t])       + __ldcg(&g_rg[t + 256]);
        for (int s2 = 128; s2; s2 >>= 1) {
            __syncthreads();
            if (t < s2) { red_c[t] += red_c[t + s2]; red_r[t] += red_r[t + s2]; }
        }
        __syncthreads();
        if (t == 0) {
            out[0] = red_c[0] * (1.0f / (float)TOTAL);
            out[1] = red_r[0] * (1.0f / (float)TOTAL);
        }
    }
}

extern "C" void kernel_launch(void* const* d_in, const int* in_sizes, int n_in,
                              void* d_out, int out_size) {
    const float* props = (const float*)d_in[1];
    const float* score = (const float*)d_in[2];
    const float* txty  = (const float*)d_in[3];
    const float* gts   = (const float*)d_in[4];
    const int*   glbl  = (const int*)d_in[5];
    float* out = (float*)d_out;
    int n_gt = in_sizes[4] / 4;

    k_fused<<<NBLK, TPB>>>(props, gts, glbl, score, txty, out, n_gt);
}